// round 12
// baseline (speedup 1.0000x reference)
#include <cuda_runtime.h>
#include <cuda_bf16.h>
#include <math.h>
#include <stdint.h>

#define NN 50000
#define EE 600000
#define DD 128
#define LL 4

// ---- scratch (allocation-free __device__ globals) ----
// X activations, bf16 hi/lo split, stride 128, PING-PONG buffers:
// layer l reads buf[l&1], writes buf[(l+1)&1]  (avoids cross-block RAW race)
__device__ __nv_bfloat16 g_Ah[2][(size_t)NN * 128];
__device__ __nv_bfloat16 g_Al[2][(size_t)NN * 128];
// B operand per layer: B[n][k] = Wfull[k][n], k<128 -> Wroot, k>=128 -> Wrel
__device__ __nv_bfloat16 g_Bh[LL * 128 * 256];
__device__ __nv_bfloat16 g_Bl[LL * 128 * 256];
__device__ int   g_deg[NN];
__device__ int   g_cursor[NN];
__device__ int   g_rowptr[NN + 1];
__device__ int   g_col[EE];
__device__ float g_invdeg[NN];
__device__ int   g_part[256];
__device__ int   g_partscan[256];

// ---------------- small helpers ----------------
__device__ __forceinline__ uint32_t smem_u32(const void* p) {
    uint32_t a;
    asm("{ .reg .u64 t; cvta.to.shared.u64 t, %1; cvt.u32.u64 %0, t; }" : "=r"(a) : "l"(p));
    return a;
}
__device__ __forceinline__ float2 bf2_to_f2(uint32_t u) {
    __nv_bfloat162 b = *reinterpret_cast<__nv_bfloat162*>(&u);
    return make_float2(__bfloat162float(b.x), __bfloat162float(b.y));
}
__device__ __forceinline__ void split_bf16(float v, unsigned short& hi, unsigned short& lo) {
    __nv_bfloat16 h = __float2bfloat16_rn(v);
    __nv_bfloat16 l = __float2bfloat16_rn(v - __bfloat162float(h));
    hi = *reinterpret_cast<unsigned short*>(&h);
    lo = *reinterpret_cast<unsigned short*>(&l);
}

// ---------------------------------------------------------------- CSR build
__global__ void k_zero() {
    int i = blockIdx.x * blockDim.x + threadIdx.x;
    if (i < NN) { g_deg[i] = 0; g_cursor[i] = 0; }
}
__global__ void k_deg(const int* __restrict__ dst) {
    int e = blockIdx.x * blockDim.x + threadIdx.x;
    if (e < EE) atomicAdd(&g_deg[dst[e]], 1);
}
__global__ void k_s1() {
    __shared__ int sm[256];
    int t = threadIdx.x;
    int i = blockIdx.x * 256 + t;
    int v = (i < NN) ? g_deg[i] : 0;
    if (i < NN) g_invdeg[i] = 1.0f / (float)max(v, 1);
    sm[t] = v;
    __syncthreads();
    #pragma unroll
    for (int off = 128; off > 0; off >>= 1) {
        if (t < off) sm[t] += sm[t + off];
        __syncthreads();
    }
    if (t == 0) g_part[blockIdx.x] = sm[0];
}
__global__ void k_s2(int nblk) {
    __shared__ int sm[256];
    int t = threadIdx.x;
    int v = (t < nblk) ? g_part[t] : 0;
    sm[t] = v;
    __syncthreads();
    #pragma unroll
    for (int off = 1; off < 256; off <<= 1) {
        int x = sm[t];
        int y = (t >= off) ? sm[t - off] : 0;
        __syncthreads();
        sm[t] = x + y;
        __syncthreads();
    }
    if (t < nblk) g_partscan[t] = sm[t] - v;
    if (t == 0) g_rowptr[NN] = EE;
}
__global__ void k_s3() {
    __shared__ int sm[256];
    int t = threadIdx.x;
    int i = blockIdx.x * 256 + t;
    int v = (i < NN) ? g_deg[i] : 0;
    sm[t] = v;
    __syncthreads();
    #pragma unroll
    for (int off = 1; off < 256; off <<= 1) {
        int x = sm[t];
        int y = (t >= off) ? sm[t - off] : 0;
        __syncthreads();
        sm[t] = x + y;
        __syncthreads();
    }
    if (i < NN) g_rowptr[i] = g_partscan[blockIdx.x] + sm[t] - v;
}
__global__ void k_fill(const int* __restrict__ src, const int* __restrict__ dst) {
    int e = blockIdx.x * blockDim.x + threadIdx.x;
    if (e < EE) {
        int d = dst[e];
        int p = atomicAdd(&g_cursor[d], 1);
        g_col[g_rowptr[d] + p] = src[e];
    }
}
__global__ void k_sort() {
    int i = blockIdx.x * blockDim.x + threadIdx.x;
    if (i >= NN) return;
    int beg = g_rowptr[i], end = g_rowptr[i + 1];
    for (int a = beg + 1; a < end; ++a) {
        int v = g_col[a];
        int b = a - 1;
        while (b >= beg && g_col[b] > v) { g_col[b + 1] = g_col[b]; --b; }
        g_col[b + 1] = v;
    }
}

// ---------------------------------------------------------------- converts
// layer-0 X -> bf16 hi/lo into buf 0 (stride 128)
__global__ void k_convA(const float* __restrict__ x) {
    int idx = blockIdx.x * blockDim.x + threadIdx.x;   // 0 .. NN*32-1
    if (idx >= NN * 32) return;
    int i4 = idx * 4;
    float4 v = *reinterpret_cast<const float4*>(&x[i4]);
    unsigned short h[4], l[4];
    split_bf16(v.x, h[0], l[0]);
    split_bf16(v.y, h[1], l[1]);
    split_bf16(v.z, h[2], l[2]);
    split_bf16(v.w, h[3], l[3]);
    size_t o = (size_t)i4;
    *reinterpret_cast<uint2*>(&g_Ah[0][o]) = make_uint2((uint32_t)h[0] | ((uint32_t)h[1] << 16),
                                                        (uint32_t)h[2] | ((uint32_t)h[3] << 16));
    *reinterpret_cast<uint2*>(&g_Al[0][o]) = make_uint2((uint32_t)l[0] | ((uint32_t)l[1] << 16),
                                                        (uint32_t)l[2] | ((uint32_t)l[3] << 16));
}

__global__ void k_convW(const float* __restrict__ Wroot, const float* __restrict__ Wrel) {
    int idx = blockIdx.x * blockDim.x + threadIdx.x;   // LL*256*128
    if (idx >= LL * 256 * 128) return;
    int l = idx >> 15;
    int r = idx & 32767;
    int k = r >> 7, n = r & 127;
    float w = (k < 128) ? Wroot[l * 16384 + k * 128 + n]
                        : Wrel[l * 16384 + (k - 128) * 128 + n];
    unsigned short h, lo;
    split_bf16(w, h, lo);
    size_t o = (size_t)l * 32768 + (size_t)n * 256 + k;
    *reinterpret_cast<unsigned short*>(&g_Bh[o]) = h;
    *reinterpret_cast<unsigned short*>(&g_Bl[o]) = lo;
}

// ---------------------------------------------------------------- fused layer
// Per block: 128 rows. A = [X(cols 0-127) | mean-agg(cols 128-255)] bf16 hi/lo,
// B = [Wroot; Wrel]^T. Chunks 0,1 of A load X from the READ buffer; chunks 2,3
// gather neighbors (READ buffer) in-block. Epilogue writes the WRITE buffer.
#define SM_AH    0
#define SM_AL    16384
#define SM_BH    32768
#define SM_BL    49152
#define SM_TOTAL 65536

__device__ __forceinline__ void load_tileA(char* smem, int smOff,
                                           const __nv_bfloat16* __restrict__ gbase,
                                           int rowBase, int k0, int tid) {
    #pragma unroll
    for (int i = 0; i < 4; ++i) {
        int s = tid + 256 * i;          // 0..1023 16-byte slots
        int r = s >> 3;
        int c8 = s & 7;
        int row = rowBase + r;
        if (row > NN - 1) row = NN - 1;
        uint4 v = *reinterpret_cast<const uint4*>(&gbase[(size_t)row * 128 + k0 + c8 * 8]);
        uint32_t byte = r * 128 + c8 * 16;
        uint32_t sw = byte ^ ((byte >> 3) & 0x70);
        *reinterpret_cast<uint4*>(smem + smOff + sw) = v;
    }
}
__device__ __forceinline__ void load_tileW(char* smem, int smOff,
                                           const __nv_bfloat16* __restrict__ gbase,
                                           int k0, int tid) {
    #pragma unroll
    for (int i = 0; i < 4; ++i) {
        int s = tid + 256 * i;
        int r = s >> 3;
        int c8 = s & 7;
        uint4 v = *reinterpret_cast<const uint4*>(&gbase[(size_t)r * 256 + k0 + c8 * 8]);
        uint32_t byte = r * 128 + c8 * 16;
        uint32_t sw = byte ^ ((byte >> 3) & 0x70);
        *reinterpret_cast<uint4*>(smem + smOff + sw) = v;
    }
}

__device__ __forceinline__ void ldsm4(uint32_t* r, uint32_t addr) {
    asm volatile("ldmatrix.sync.aligned.m8n8.x4.shared.b16 {%0,%1,%2,%3}, [%4];"
                 : "=r"(r[0]), "=r"(r[1]), "=r"(r[2]), "=r"(r[3]) : "r"(addr));
}
__device__ __forceinline__ void mma16816(float* c, const uint32_t* a,
                                         uint32_t b0, uint32_t b1) {
    asm volatile(
        "mma.sync.aligned.m16n8k16.row.col.f32.bf16.bf16.f32 "
        "{%0,%1,%2,%3}, {%4,%5,%6,%7}, {%8,%9}, {%0,%1,%2,%3};"
        : "+f"(c[0]), "+f"(c[1]), "+f"(c[2]), "+f"(c[3])
        : "r"(a[0]), "r"(a[1]), "r"(a[2]), "r"(a[3]), "r"(b0), "r"(b1));
}

__global__ __launch_bounds__(256) void k_layer(
    const float* __restrict__ bias, float* __restrict__ final_out, int l)
{
    extern __shared__ char smem[];
    uint32_t smem_base = smem_u32(smem);
    int tid = threadIdx.x;
    int wid = tid >> 5;
    int lane = tid & 31;
    int rowBase = blockIdx.x * 128;
    int mbase = (wid & 3) * 32;     // warp's 32-row group (mma)
    int nbase = (wid >> 2) * 64;    // warp's 64-col group (mma)

    const __nv_bfloat16* RAh = g_Ah[l & 1];       // read buffer
    const __nv_bfloat16* RAl = g_Al[l & 1];
    __nv_bfloat16* WAh = g_Ah[(l + 1) & 1];       // write buffer
    __nv_bfloat16* WAl = g_Al[(l + 1) & 1];

    const __nv_bfloat16* Bh = g_Bh + (size_t)l * 32768;
    const __nv_bfloat16* Bl = g_Bl + (size_t)l * 32768;

    float acc[2][8][4];
    #pragma unroll
    for (int i = 0; i < 2; ++i)
        #pragma unroll
        for (int j = 0; j < 8; ++j)
            #pragma unroll
            for (int q = 0; q < 4; ++q) acc[i][j][q] = 0.f;

    int lrow = lane & 15;
    int lkb = (lane >> 4) * 16;     // 0 or 16 bytes (k 0-7 / 8-15)

    #pragma unroll 1
    for (int chunk = 0; chunk < 4; ++chunk) {
        int k0 = chunk * 64;
        if (chunk < 2) {
            load_tileA(smem, SM_AH, RAh, rowBase, k0, tid);
            load_tileA(smem, SM_AL, RAl, rowBase, k0, tid);
        } else {
            // in-block agg gather: warp handles 16 rows, lane handles 2 cols
            int c0 = (chunk - 2) * 64 + lane * 2;   // col in 0..127
            #pragma unroll 1
            for (int rr = 0; rr < 16; ++rr) {
                int r = wid * 16 + rr;
                int node = rowBase + r;
                float s0 = 0.f, s1 = 0.f;
                if (node < NN) {
                    int e = g_rowptr[node], end = g_rowptr[node + 1];
                    for (; e + 3 < end; e += 4) {
                        int n0 = g_col[e],     n1 = g_col[e + 1];
                        int n2 = g_col[e + 2], n3 = g_col[e + 3];
                        uint32_t h0 = *reinterpret_cast<const uint32_t*>(&RAh[(size_t)n0 * 128 + c0]);
                        uint32_t h1 = *reinterpret_cast<const uint32_t*>(&RAh[(size_t)n1 * 128 + c0]);
                        uint32_t h2 = *reinterpret_cast<const uint32_t*>(&RAh[(size_t)n2 * 128 + c0]);
                        uint32_t h3 = *reinterpret_cast<const uint32_t*>(&RAh[(size_t)n3 * 128 + c0]);
                        uint32_t q0 = *reinterpret_cast<const uint32_t*>(&RAl[(size_t)n0 * 128 + c0]);
                        uint32_t q1 = *reinterpret_cast<const uint32_t*>(&RAl[(size_t)n1 * 128 + c0]);
                        uint32_t q2 = *reinterpret_cast<const uint32_t*>(&RAl[(size_t)n2 * 128 + c0]);
                        uint32_t q3 = *reinterpret_cast<const uint32_t*>(&RAl[(size_t)n3 * 128 + c0]);
                        float2 a0 = bf2_to_f2(h0), a1 = bf2_to_f2(h1);
                        float2 a2 = bf2_to_f2(h2), a3 = bf2_to_f2(h3);
                        float2 b0 = bf2_to_f2(q0), b1 = bf2_to_f2(q1);
                        float2 b2 = bf2_to_f2(q2), b3 = bf2_to_f2(q3);
                        s0 += (a0.x + b0.x) + (a1.x + b1.x) + (a2.x + b2.x) + (a3.x + b3.x);
                        s1 += (a0.y + b0.y) + (a1.y + b1.y) + (a2.y + b2.y) + (a3.y + b3.y);
                    }
                    for (; e < end; ++e) {
                        int nb = g_col[e];
                        uint32_t hv = *reinterpret_cast<const uint32_t*>(&RAh[(size_t)nb * 128 + c0]);
                        uint32_t lv = *reinterpret_cast<const uint32_t*>(&RAl[(size_t)nb * 128 + c0]);
                        float2 h = bf2_to_f2(hv), lo2 = bf2_to_f2(lv);
                        s0 += h.x + lo2.x;
                        s1 += h.y + lo2.y;
                    }
                    float inv = g_invdeg[node];
                    s0 *= inv; s1 *= inv;
                }
                unsigned short h0, l0, h1, l1;
                split_bf16(s0, h0, l0);
                split_bf16(s1, h1, l1);
                uint32_t byte = (uint32_t)r * 128 + lane * 4;
                uint32_t sw = byte ^ ((byte >> 3) & 0x70);
                *reinterpret_cast<uint32_t*>(smem + SM_AH + sw) = (uint32_t)h0 | ((uint32_t)h1 << 16);
                *reinterpret_cast<uint32_t*>(smem + SM_AL + sw) = (uint32_t)l0 | ((uint32_t)l1 << 16);
            }
        }
        load_tileW(smem, SM_BH, Bh, k0, tid);
        load_tileW(smem, SM_BL, Bl, k0, tid);
        __syncthreads();

        #pragma unroll
        for (int kk = 0; kk < 4; ++kk) {
            int cb = kk * 32 + lkb;
            uint32_t ah[2][4], al[2][4];
            #pragma unroll
            for (int mt = 0; mt < 2; ++mt) {
                uint32_t byte = (uint32_t)(mbase + mt * 16 + lrow) * 128 + cb;
                uint32_t sw = byte ^ ((byte >> 3) & 0x70);
                ldsm4(ah[mt], smem_base + SM_AH + sw);
                ldsm4(al[mt], smem_base + SM_AL + sw);
            }
            uint32_t bh[4][4], bl[4][4];
            #pragma unroll
            for (int nt = 0; nt < 4; ++nt) {
                uint32_t byte = (uint32_t)(nbase + nt * 16 + lrow) * 128 + cb;
                uint32_t sw = byte ^ ((byte >> 3) & 0x70);
                ldsm4(bh[nt], smem_base + SM_BH + sw);
                ldsm4(bl[nt], smem_base + SM_BL + sw);
            }
            #pragma unroll
            for (int mt = 0; mt < 2; ++mt) {
                #pragma unroll
                for (int nj = 0; nj < 8; ++nj) {
                    int nt = nj >> 1, odd = nj & 1;
                    mma16816(acc[mt][nj], ah[mt], bh[nt][odd], bh[nt][2 + odd]);
                    mma16816(acc[mt][nj], ah[mt], bl[nt][odd], bl[nt][2 + odd]);
                    mma16816(acc[mt][nj], al[mt], bh[nt][odd], bh[nt][2 + odd]);
                }
            }
        }
        __syncthreads();
    }

    // epilogue: bias + ELU + store (final fp32, else split hi/lo into WRITE buf)
    int group = lane >> 2;
    int tig = lane & 3;
    #pragma unroll
    for (int mt = 0; mt < 2; ++mt) {
        #pragma unroll
        for (int half = 0; half < 2; ++half) {
            int row = rowBase + mbase + mt * 16 + half * 8 + group;
            if (row >= NN) continue;
            #pragma unroll
            for (int nj = 0; nj < 8; ++nj) {
                int col = nbase + nj * 8 + tig * 2;
                float v0 = acc[mt][nj][half * 2]     + bias[col];
                float v1 = acc[mt][nj][half * 2 + 1] + bias[col + 1];
                v0 = (v0 > 0.f) ? v0 : expm1f(v0);
                v1 = (v1 > 0.f) ? v1 : expm1f(v1);
                if (l == LL - 1) {
                    float2 o = make_float2(v0, v1);
                    *reinterpret_cast<float2*>(&final_out[(size_t)row * 128 + col]) = o;
                } else {
                    unsigned short h0, l0, h1, l1;
                    split_bf16(v0, h0, l0);
                    split_bf16(v1, h1, l1);
                    size_t o = (size_t)row * 128 + col;
                    *reinterpret_cast<uint32_t*>(&WAh[o]) = (uint32_t)h0 | ((uint32_t)h1 << 16);
                    *reinterpret_cast<uint32_t*>(&WAl[o]) = (uint32_t)l0 | ((uint32_t)l1 << 16);
                }
            }
        }
    }
}

// ---------------------------------------------------------------- launch
extern "C" void kernel_launch(void* const* d_in, const int* in_sizes, int n_in,
                              void* d_out, int out_size) {
    const float* node_embedding = (const float*)d_in[0];
    const int*   edge_index     = (const int*)d_in[1];
    const float* Ws_rel         = (const float*)d_in[2];
    const float* bs_rel         = (const float*)d_in[3];
    const float* Ws_root        = (const float*)d_in[4];
    float* out = (float*)d_out;

    const int* src = edge_index;
    const int* dst = edge_index + EE;

    cudaFuncSetAttribute(k_layer, cudaFuncAttributeMaxDynamicSharedMemorySize, SM_TOTAL);

    int nScanBlk = (NN + 255) / 256;   // 196

    k_zero<<<nScanBlk, 256>>>();
    k_deg<<<(EE + 255) / 256, 256>>>(dst);
    k_s1<<<nScanBlk, 256>>>();
    k_s2<<<1, 256>>>(nScanBlk);
    k_s3<<<nScanBlk, 256>>>();
    k_fill<<<(EE + 255) / 256, 256>>>(src, dst);
    k_sort<<<nScanBlk, 256>>>();
    k_convA<<<(NN * 32 + 255) / 256, 256>>>(node_embedding);
    k_convW<<<(LL * 256 * 128 + 255) / 256, 256>>>(Ws_root, Ws_rel);

    int layerBlocks = (NN + 127) / 128;   // 391

    for (int l = 0; l < LL; ++l) {
        k_layer<<<layerBlocks, 256, SM_TOTAL>>>(bs_rel + (size_t)l * DD, out, l);
    }
}